// round 2
// baseline (speedup 1.0000x reference)
#include <cuda_runtime.h>
#include <math.h>

// Problem constants
#define BB   4
#define CCH  256
#define CIN  128
#define CINT 16
#define HH2  128          // output spatial H = W
#define HWSZ 16384        // 128*128
#define NEGINF (-1000000000.0f)

// ---------------- scratch (device globals: no allocation allowed) ----------------
__device__ float g_highup[16777216];  // (4,256,128,128)
__device__ float g_query [ 8388608];  // (4,128,128,128)
__device__ float g_value [ 8388608];
__device__ float g_pv    [ 8388608];
__device__ float g_tmp   [ 8388608];
__device__ float g_pq    [ 1048576];  // (4,16,128,128)
__device__ float g_pk    [ 1048576];
__device__ float g_att   [16777216];  // (4,128,128,256)

// ---------------- bilinear 2x upsample, half-pixel centers, clamped ----------------
__global__ __launch_bounds__(256) void upsample_kernel(const float* __restrict__ in,
                                                       float* __restrict__ out) {
    int idx = blockIdx.x * 256 + threadIdx.x;       // 0 .. 16777215
    int ox = idx & 127;
    int oy = (idx >> 7) & 127;
    int bc = idx >> 14;
    float fy = 0.5f * oy - 0.25f;
    float fx = 0.5f * ox - 0.25f;
    int y0 = (int)floorf(fy); float wy = fy - (float)y0;
    int x0 = (int)floorf(fx); float wx = fx - (float)x0;
    int y1 = min(y0 + 1, 63); y0 = max(y0, 0);
    int x1 = min(x0 + 1, 63); x0 = max(x0, 0);
    const float* p = in + (size_t)bc * 4096;
    float v00 = p[y0 * 64 + x0], v01 = p[y0 * 64 + x1];
    float v10 = p[y1 * 64 + x0], v11 = p[y1 * 64 + x1];
    float top = v00 + wx * (v01 - v00);
    float bot = v10 + wx * (v11 - v10);
    out[idx] = top + wy * (bot - top);
}

// ---------------- generic tiled SGEMM: Y[b,o,p] (+)= sum_i W[o, coff+i] * X[b,i,p] ----------------
// BM=BN=128, BK=8, 256 threads, 8x8 microtile. Optional bias / accumulate / BN+ReLU epilogue.
__global__ __launch_bounds__(256) void gemm_big(
    const float* __restrict__ Wm, int ldw, int coff,
    const float* __restrict__ bias,
    const float* __restrict__ X, int I,
    const float* __restrict__ Yin, float* __restrict__ Yout,
    int O, int accum,
    const float* __restrict__ bng, const float* __restrict__ bnb,
    const float* __restrict__ bnm, const float* __restrict__ bnv)
{
    __shared__ float As[8][128];
    __shared__ float Bs[8][128];
    const int b  = blockIdx.z;
    const int to = blockIdx.y * 128;
    const int tp = blockIdx.x * 128;
    const int tid = threadIdx.x;

    const int a_m = tid >> 1;            // 0..127
    const int a_k = (tid & 1) * 4;       // 0 or 4
    const int b_k = tid >> 5;            // 0..7
    const int b_n = (tid & 31) * 4;      // 0..124
    const int m0 = (tid >> 4) * 8;
    const int n0 = (tid & 15) * 8;

    float acc[8][8] = {};
    const float* Wp = Wm + (size_t)(to + a_m) * ldw + coff + a_k;
    const float* Xp = X + ((size_t)b * I + b_k) * (size_t)HWSZ + tp + b_n;

    for (int k0 = 0; k0 < I; k0 += 8) {
        float4 av = *(const float4*)(Wp + k0);
        As[a_k + 0][a_m] = av.x;
        As[a_k + 1][a_m] = av.y;
        As[a_k + 2][a_m] = av.z;
        As[a_k + 3][a_m] = av.w;
        float4 bv = *(const float4*)(Xp + (size_t)k0 * HWSZ);
        *(float4*)&Bs[b_k][b_n] = bv;
        __syncthreads();
#pragma unroll
        for (int kk = 0; kk < 8; kk++) {
            float a[8], c[8];
            *(float4*)(a)     = *(const float4*)&As[kk][m0];
            *(float4*)(a + 4) = *(const float4*)&As[kk][m0 + 4];
            *(float4*)(c)     = *(const float4*)&Bs[kk][n0];
            *(float4*)(c + 4) = *(const float4*)&Bs[kk][n0 + 4];
#pragma unroll
            for (int i = 0; i < 8; i++)
#pragma unroll
                for (int j = 0; j < 8; j++)
                    acc[i][j] += a[i] * c[j];
        }
        __syncthreads();
    }

#pragma unroll
    for (int i = 0; i < 8; i++) {
        int o = to + m0 + i;
        float bia = bias ? bias[o] : 0.0f;
        float scale = 1.0f, mean = 0.0f, beta = 0.0f;
        bool dobn = (bng != nullptr);
        if (dobn) {
            scale = bng[o] * rsqrtf(bnv[o] + 1e-5f);
            mean  = bnm[o];
            beta  = bnb[o];
        }
        size_t base = ((size_t)b * O + o) * HWSZ + tp + n0;
#pragma unroll
        for (int j = 0; j < 8; j++) {
            float v = acc[i][j] + bia;
            if (accum) v += Yin[base + j];
            if (dobn)  v = fmaxf((v - mean) * scale + beta, 0.0f);
            Yout[base + j] = v;
        }
    }
}

// ---------------- small projection: O=16, I=128 (pq / pk) ----------------
__global__ __launch_bounds__(256) void proj16_kernel(
    const float* __restrict__ Wm, const float* __restrict__ bias,
    const float* __restrict__ X, float* __restrict__ Y)
{
    __shared__ float Ws[16 * 128];
    const int b = blockIdx.y;
    const int p = blockIdx.x * 256 + threadIdx.x;
    for (int i = threadIdx.x; i < 2048; i += 256) Ws[i] = Wm[i];
    __syncthreads();
    float acc[16];
#pragma unroll
    for (int o = 0; o < 16; o++) acc[o] = bias[o];
    const float* Xp = X + (size_t)b * CIN * HWSZ + p;
#pragma unroll 4
    for (int i = 0; i < 128; i++) {
        float xv = Xp[(size_t)i * HWSZ];
#pragma unroll
        for (int o = 0; o < 16; o++) acc[o] += Ws[o * 128 + i] * xv;
    }
    float* Yp = Y + (size_t)b * 16 * HWSZ + p;
#pragma unroll
    for (int o = 0; o < 16; o++) Yp[(size_t)o * HWSZ] = acc[o];
}

// ---------------- criss-cross logits ----------------
// eH[b,h,w,x] = sum_c pq[b,c,h,w]*pk[b,c,x,w]  (+NEG_INF on h==x). One block per (b,w).
__global__ __launch_bounds__(256) void eH_kernel(const float* __restrict__ pq,
                                                 const float* __restrict__ pk,
                                                 float* __restrict__ att)
{
    __shared__ float PQ[16][128];
    __shared__ float PK[16][128];
    const int w = blockIdx.x, b = blockIdx.y;
    for (int i = threadIdx.x; i < 2048; i += 256) {
        int c = i >> 7, h = i & 127;
        size_t idx = (((size_t)b * 16 + c) * 128 + h) * 128 + w;
        PQ[c][h] = pq[idx];
        PK[c][h] = pk[idx];
    }
    __syncthreads();
    const int x  = threadIdx.x & 127;
    const int h0 = threadIdx.x >> 7;
    for (int h = h0; h < 128; h += 2) {
        float s = 0.0f;
#pragma unroll
        for (int c = 0; c < 16; c++) s += PQ[c][h] * PK[c][x];
        if (h == x) s += NEGINF;
        att[(((size_t)b * 128 + h) * 128 + w) * 256 + x] = s;
    }
}

// eW[b,h,w,x] = sum_c pq[b,c,h,w]*pk[b,c,h,x]. One block per (b,h).
__global__ __launch_bounds__(256) void eW_kernel(const float* __restrict__ pq,
                                                 const float* __restrict__ pk,
                                                 float* __restrict__ att)
{
    __shared__ float PQ[16][128];
    __shared__ float PK[16][128];
    const int h = blockIdx.x, b = blockIdx.y;
    for (int i = threadIdx.x; i < 2048; i += 256) {
        int c = i >> 7, w = i & 127;
        size_t idx = (((size_t)b * 16 + c) * 128 + h) * 128 + w;
        PQ[c][w] = pq[idx];
        PK[c][w] = pk[idx];
    }
    __syncthreads();
    const int x  = threadIdx.x & 127;
    const int w0 = threadIdx.x >> 7;
    for (int w = w0; w < 128; w += 2) {
        float s = 0.0f;
#pragma unroll
        for (int c = 0; c < 16; c++) s += PQ[c][w] * PK[c][x];
        att[(((size_t)b * 128 + h) * 128 + w) * 256 + 128 + x] = s;
    }
}

// ---------------- softmax over last dim (256), one warp per row ----------------
__global__ __launch_bounds__(256) void softmax_kernel(float* __restrict__ att)
{
    const int warp = threadIdx.x >> 5;
    const int lane = threadIdx.x & 31;
    const size_t row = (size_t)blockIdx.x * 8 + warp;
    float* r = att + row * 256;
    float v[8];
    float mx = -INFINITY;
#pragma unroll
    for (int j = 0; j < 8; j++) { v[j] = r[lane + 32 * j]; mx = fmaxf(mx, v[j]); }
#pragma unroll
    for (int o = 16; o; o >>= 1) mx = fmaxf(mx, __shfl_xor_sync(0xffffffffu, mx, o));
    float s = 0.0f;
#pragma unroll
    for (int j = 0; j < 8; j++) { v[j] = __expf(v[j] - mx); s += v[j]; }
#pragma unroll
    for (int o = 16; o; o >>= 1) s += __shfl_xor_sync(0xffffffffu, s, o);
    float inv = 1.0f / s;
#pragma unroll
    for (int j = 0; j < 8; j++) r[lane + 32 * j] = v[j] * inv;
}

// ---------------- aggregation H: tmp[b,c,h,w] = sum_x pv[b,c,x,w]*attH[b,h,w,x] ----------------
// One block per (b,w): 128x128x128 GEMM, 8x8 microtile.
__global__ __launch_bounds__(256) void aggH_kernel(const float* __restrict__ pv,
                                                   const float* __restrict__ att,
                                                   float* __restrict__ tmp)
{
    __shared__ float As[8][128];   // [kk][c]  pv[b,c,x0+kk,w]
    __shared__ float Bs[8][128];   // [kk][h]  attH[b,h,w,x0+kk]
    const int w = blockIdx.x, b = blockIdx.y;
    const int tid = threadIdx.x;
    const int a_m = tid >> 1;
    const int a_k = (tid & 1) * 4;
    const int m0 = (tid >> 4) * 8;
    const int n0 = (tid & 15) * 8;
    float acc[8][8] = {};
    const float* atp = att + (((size_t)b * 128 + a_m) * 128 + w) * 256 + a_k;
    const float* pvp = pv + ((size_t)b * 128 + a_m) * HWSZ + w;
    for (int x0 = 0; x0 < 128; x0 += 8) {
        // pv strided loads
        As[a_k + 0][a_m] = pvp[(size_t)(x0 + a_k + 0) * 128];
        As[a_k + 1][a_m] = pvp[(size_t)(x0 + a_k + 1) * 128];
        As[a_k + 2][a_m] = pvp[(size_t)(x0 + a_k + 2) * 128];
        As[a_k + 3][a_m] = pvp[(size_t)(x0 + a_k + 3) * 128];
        float4 bv = *(const float4*)(atp + x0);
        Bs[a_k + 0][a_m] = bv.x;
        Bs[a_k + 1][a_m] = bv.y;
        Bs[a_k + 2][a_m] = bv.z;
        Bs[a_k + 3][a_m] = bv.w;
        __syncthreads();
#pragma unroll
        for (int kk = 0; kk < 8; kk++) {
            float a[8], c[8];
            *(float4*)(a)     = *(const float4*)&As[kk][m0];
            *(float4*)(a + 4) = *(const float4*)&As[kk][m0 + 4];
            *(float4*)(c)     = *(const float4*)&Bs[kk][n0];
            *(float4*)(c + 4) = *(const float4*)&Bs[kk][n0 + 4];
#pragma unroll
            for (int i = 0; i < 8; i++)
#pragma unroll
                for (int j = 0; j < 8; j++)
                    acc[i][j] += a[i] * c[j];
        }
        __syncthreads();
    }
#pragma unroll
    for (int i = 0; i < 8; i++)
#pragma unroll
        for (int j = 0; j < 8; j++)
            tmp[(((size_t)b * 128 + m0 + i) * 128 + (n0 + j)) * 128 + w] = acc[i][j];
}

// ---------------- aggregation W + update:
// value[b,c,h,w] = gamma*(tmp + sum_x pv[b,c,h,x]*attW[b,h,w,x]) + value[b,c,h,w]
// One block per (b,h).
__global__ __launch_bounds__(256) void aggW_kernel(const float* __restrict__ pv,
                                                   const float* __restrict__ att,
                                                   const float* __restrict__ tmp,
                                                   float* __restrict__ value,
                                                   const float* __restrict__ gamma_p)
{
    __shared__ float As[8][128];   // [kk][c]  pv[b,c,h,x0+kk]
    __shared__ float Bs[8][128];   // [kk][w]  attW[b,h,w,x0+kk]
    const int h = blockIdx.x, b = blockIdx.y;
    const int tid = threadIdx.x;
    const int a_m = tid >> 1;
    const int a_k = (tid & 1) * 4;
    const int m0 = (tid >> 4) * 8;
    const int n0 = (tid & 15) * 8;
    float acc[8][8] = {};
    const float* pvp = pv + (((size_t)b * 128 + a_m) * 128 + h) * 128 + a_k;
    const float* atp = att + (((size_t)b * 128 + h) * 128 + a_m) * 256 + 128 + a_k;
    for (int x0 = 0; x0 < 128; x0 += 8) {
        float4 av = *(const float4*)(pvp + x0);
        As[a_k + 0][a_m] = av.x;
        As[a_k + 1][a_m] = av.y;
        As[a_k + 2][a_m] = av.z;
        As[a_k + 3][a_m] = av.w;
        float4 bv = *(const float4*)(atp + x0);
        Bs[a_k + 0][a_m] = bv.x;
        Bs[a_k + 1][a_m] = bv.y;
        Bs[a_k + 2][a_m] = bv.z;
        Bs[a_k + 3][a_m] = bv.w;
        __syncthreads();
#pragma unroll
        for (int kk = 0; kk < 8; kk++) {
            float a[8], c[8];
            *(float4*)(a)     = *(const float4*)&As[kk][m0];
            *(float4*)(a + 4) = *(const float4*)&As[kk][m0 + 4];
            *(float4*)(c)     = *(const float4*)&Bs[kk][n0];
            *(float4*)(c + 4) = *(const float4*)&Bs[kk][n0 + 4];
#pragma unroll
            for (int i = 0; i < 8; i++)
#pragma unroll
                for (int j = 0; j < 8; j++)
                    acc[i][j] += a[i] * c[j];
        }
        __syncthreads();
    }
    const float g = *gamma_p;
#pragma unroll
    for (int i = 0; i < 8; i++) {
        size_t base = (((size_t)b * 128 + m0 + i) * 128 + h) * 128 + n0;
#pragma unroll
        for (int j = 0; j < 8; j++) {
            value[base + j] = g * (tmp[base + j] + acc[i][j]) + value[base + j];
        }
    }
}

// ---------------- launch ----------------
extern "C" void kernel_launch(void* const* d_in, const int* in_sizes, int n_in,
                              void* d_out, int out_size)
{
    const float* low   = (const float*)d_in[0];
    const float* high  = (const float*)d_in[1];
    const float* Wc1   = (const float*)d_in[2];
    const float* bc1   = (const float*)d_in[3];
    const float* Wc2   = (const float*)d_in[4];
    const float* bc2   = (const float*)d_in[5];
    const float* Wq    = (const float*)d_in[6];
    const float* bq    = (const float*)d_in[7];
    const float* Wk    = (const float*)d_in[8];
    const float* bk    = (const float*)d_in[9];
    const float* Wv    = (const float*)d_in[10];
    const float* bv    = (const float*)d_in[11];
    const float* gamma = (const float*)d_in[12];
    const float* Wb    = (const float*)d_in[13];
    const float* bng   = (const float*)d_in[14];
    const float* bnb   = (const float*)d_in[15];
    const float* bnm   = (const float*)d_in[16];
    const float* bnv   = (const float*)d_in[17];
    float* out = (float*)d_out;

    float *highup, *query, *value, *pv, *tmp, *pq, *pk, *att;
    cudaGetSymbolAddress((void**)&highup, g_highup);
    cudaGetSymbolAddress((void**)&query,  g_query);
    cudaGetSymbolAddress((void**)&value,  g_value);
    cudaGetSymbolAddress((void**)&pv,     g_pv);
    cudaGetSymbolAddress((void**)&tmp,    g_tmp);
    cudaGetSymbolAddress((void**)&pq,     g_pq);
    cudaGetSymbolAddress((void**)&pk,     g_pk);
    cudaGetSymbolAddress((void**)&att,    g_att);

    // 1. bilinear 2x upsample
    upsample_kernel<<<65536, 256>>>(high, highup);

    // 2. query = Wc1[:, :256] @ high_up + bc1 ; += Wc1[:, 256:] @ low
    gemm_big<<<dim3(128, 1, BB), 256>>>(Wc1, 512, 0,   bc1,     highup, 256,
                                        nullptr, query, 128, 0,
                                        nullptr, nullptr, nullptr, nullptr);
    gemm_big<<<dim3(128, 1, BB), 256>>>(Wc1, 512, 256, nullptr, low,    256,
                                        query, query, 128, 1,
                                        nullptr, nullptr, nullptr, nullptr);
    // 3. value = Wc2 @ high_up + bc2
    gemm_big<<<dim3(128, 1, BB), 256>>>(Wc2, 256, 0,   bc2,     highup, 256,
                                        nullptr, value, 128, 0,
                                        nullptr, nullptr, nullptr, nullptr);

    // 4. pq (query is fixed across iterations)
    proj16_kernel<<<dim3(64, BB), 256>>>(Wq, bq, query, pq);

    // 5. two criss-cross attention iterations
    for (int it = 0; it < 2; it++) {
        proj16_kernel<<<dim3(64, BB), 256>>>(Wk, bk, value, pk);
        gemm_big<<<dim3(128, 1, BB), 256>>>(Wv, 128, 0, bv, value, 128,
                                            nullptr, pv, 128, 0,
                                            nullptr, nullptr, nullptr, nullptr);
        eH_kernel<<<dim3(128, BB), 256>>>(pq, pk, att);
        eW_kernel<<<dim3(128, BB), 256>>>(pq, pk, att);
        softmax_kernel<<<8192, 256>>>(att);
        aggH_kernel<<<dim3(128, BB), 256>>>(pv, att, tmp);
        aggW_kernel<<<dim3(128, BB), 256>>>(pv, att, tmp, value, gamma);
    }

    // 6. fused = Wb[:, :128] @ value ; += Wb[:, 128:] @ high_up ; BN + ReLU
    gemm_big<<<dim3(128, 2, BB), 256>>>(Wb, 384, 0,   nullptr, value,  128,
                                        nullptr, out, 256, 0,
                                        nullptr, nullptr, nullptr, nullptr);
    gemm_big<<<dim3(128, 2, BB), 256>>>(Wb, 384, 128, nullptr, highup, 256,
                                        out, out, 256, 1,
                                        bng, bnb, bnm, bnv);
}

// round 4
// speedup vs baseline: 1.8111x; 1.8111x over previous
#include <cuda_runtime.h>
#include <math.h>

// Problem constants
#define BB   4
#define HWSZ 16384        // 128*128
#define NEGINF (-1000000000.0f)

// ---------------- scratch (device globals: no allocation allowed) ----------------
__device__ float g_highup[16777216];  // (4,256,128,128)
__device__ float g_query [ 8388608];  // (4,128,128,128)
__device__ float g_value [ 8388608];
__device__ float g_pv    [ 8388608];
__device__ float g_tmp   [ 8388608];
__device__ float g_pq    [ 1048576];  // (4,16,128,128)
__device__ float g_pk    [ 1048576];
__device__ float g_att   [16777216];  // (4,128,128,256)

// ---------------- tf32 helpers ----------------
__device__ __forceinline__ unsigned f2tf(float f) {
    unsigned r;
    asm("cvt.rna.tf32.f32 %0, %1;" : "=r"(r) : "f"(f));
    return r;
}

__device__ __forceinline__ void mma8(float* d, const unsigned* a, const unsigned* b) {
    asm("mma.sync.aligned.m16n8k8.row.col.f32.tf32.tf32.f32 "
        "{%0,%1,%2,%3},{%4,%5,%6,%7},{%8,%9},{%0,%1,%2,%3};"
        : "+f"(d[0]), "+f"(d[1]), "+f"(d[2]), "+f"(d[3])
        : "r"(a[0]), "r"(a[1]), "r"(a[2]), "r"(a[3]), "r"(b[0]), "r"(b[1]));
}

// Compute one K=16 chunk from staged smem tiles. Warp tile 64x32 (4 m-tiles x 4 n-tiles).
// As[k][m], Bs[k][n], stride 136 words -> conflict-free fragment loads.
__device__ __forceinline__ void tile_mma(const unsigned (*As)[136],
                                         const unsigned (*Bs)[136],
                                         float acc[4][4][4],
                                         int lane, int mbase, int nbase)
{
#pragma unroll
    for (int kt = 0; kt < 2; kt++) {
        unsigned a[4][4], b[4][2];
        const int kb = kt * 8 + (lane & 3);
        const int rq = lane >> 2;
#pragma unroll
        for (int mt = 0; mt < 4; mt++) {
            int m = mbase + mt * 16 + rq;
            a[mt][0] = As[kb][m];
            a[mt][1] = As[kb][m + 8];
            a[mt][2] = As[kb + 4][m];
            a[mt][3] = As[kb + 4][m + 8];
        }
#pragma unroll
        for (int nt = 0; nt < 4; nt++) {
            int n = nbase + nt * 8 + rq;
            b[nt][0] = Bs[kb][n];
            b[nt][1] = Bs[kb + 4][n];
        }
#pragma unroll
        for (int mt = 0; mt < 4; mt++)
#pragma unroll
            for (int nt = 0; nt < 4; nt++)
                mma8(acc[mt][nt], a[mt], b[nt]);
    }
}

// ---------------- bilinear 2x upsample ----------------
__global__ __launch_bounds__(256) void upsample_kernel(const float* __restrict__ in,
                                                       float* __restrict__ out) {
    int idx = blockIdx.x * 256 + threadIdx.x;
    int ox = idx & 127;
    int oy = (idx >> 7) & 127;
    int bc = idx >> 14;
    float fy = 0.5f * oy - 0.25f;
    float fx = 0.5f * ox - 0.25f;
    int y0 = (int)floorf(fy); float wy = fy - (float)y0;
    int x0 = (int)floorf(fx); float wx = fx - (float)x0;
    int y1 = min(y0 + 1, 63); y0 = max(y0, 0);
    int x1 = min(x0 + 1, 63); x0 = max(x0, 0);
    const float* p = in + (size_t)bc * 4096;
    float v00 = p[y0 * 64 + x0], v01 = p[y0 * 64 + x1];
    float v10 = p[y1 * 64 + x0], v11 = p[y1 * 64 + x1];
    float top = v00 + wx * (v01 - v00);
    float bot = v10 + wx * (v11 - v10);
    out[idx] = top + wy * (bot - top);
}

// ---------------- dual-input tf32 GEMM ----------------
// Y[b,o,p] = sum_i W[o,i]*Xcat[b,i,p], Xcat = concat(X1[I1], X2[I2]) along channels.
// Optional bias, optional BN+ReLU epilogue.
__global__ __launch_bounds__(256) void gemm_dual(
    const float* __restrict__ Wm, int ldw,
    const float* __restrict__ bias,
    const float* __restrict__ X1, int I1,
    const float* __restrict__ X2, int I2,
    float* __restrict__ Y, int O,
    const float* __restrict__ bng, const float* __restrict__ bnb,
    const float* __restrict__ bnm, const float* __restrict__ bnv)
{
    __shared__ unsigned As[16][136];
    __shared__ unsigned Bs[16][136];
    const int b  = blockIdx.z;
    const int to = blockIdx.y * 128;
    const int tp = blockIdx.x * 128;
    const int tid  = threadIdx.x;
    const int warp = tid >> 5;
    const int lane = tid & 31;
    const int mbase = (warp >> 2) * 64;
    const int nbase = (warp & 3) * 32;

    const int am  = tid >> 1;
    const int akq = (tid & 1) * 8;
    const int bk  = tid >> 4;
    const int bn  = (tid & 15) * 8;

    const float* X1p = X1 + (size_t)b * I1 * HWSZ;
    const float* X2p = X2 ? X2 + (size_t)b * I2 * HWSZ : nullptr;
    const int K = I1 + I2;

    float acc[4][4][4] = {};

    for (int k0 = 0; k0 < K; k0 += 16) {
        // global loads
        const float* Wp = Wm + (size_t)(to + am) * ldw + k0 + akq;
        float4 w0 = *(const float4*)Wp;
        float4 w1 = *(const float4*)(Wp + 4);
        int kr = k0 + bk;
        const float* Xp = (kr < I1) ? (X1p + (size_t)kr * HWSZ)
                                    : (X2p + (size_t)(kr - I1) * HWSZ);
        Xp += tp + bn;
        float4 x0 = *(const float4*)Xp;
        float4 x1 = *(const float4*)(Xp + 4);

        __syncthreads();
        As[akq + 0][am] = f2tf(w0.x);
        As[akq + 1][am] = f2tf(w0.y);
        As[akq + 2][am] = f2tf(w0.z);
        As[akq + 3][am] = f2tf(w0.w);
        As[akq + 4][am] = f2tf(w1.x);
        As[akq + 5][am] = f2tf(w1.y);
        As[akq + 6][am] = f2tf(w1.z);
        As[akq + 7][am] = f2tf(w1.w);
        *(uint4*)&Bs[bk][bn]     = make_uint4(f2tf(x0.x), f2tf(x0.y), f2tf(x0.z), f2tf(x0.w));
        *(uint4*)&Bs[bk][bn + 4] = make_uint4(f2tf(x1.x), f2tf(x1.y), f2tf(x1.z), f2tf(x1.w));
        __syncthreads();

        tile_mma(As, Bs, acc, lane, mbase, nbase);
    }

    const bool dobn = (bng != nullptr);
#pragma unroll
    for (int mt = 0; mt < 4; mt++) {
#pragma unroll
        for (int half = 0; half < 2; half++) {
            int o = to + mbase + mt * 16 + (lane >> 2) + half * 8;
            float bia = bias ? bias[o] : 0.0f;
            float sc = 1.0f, mn = 0.0f, bt = 0.0f;
            if (dobn) {
                sc = bng[o] * rsqrtf(bnv[o] + 1e-5f);
                mn = bnm[o];
                bt = bnb[o];
            }
            size_t rowb = ((size_t)b * O + o) * HWSZ + tp;
#pragma unroll
            for (int nt = 0; nt < 4; nt++) {
                int n = nbase + nt * 8 + 2 * (lane & 3);
                float v0 = acc[mt][nt][half * 2 + 0] + bia;
                float v1 = acc[mt][nt][half * 2 + 1] + bia;
                if (dobn) {
                    v0 = fmaxf((v0 - mn) * sc + bt, 0.0f);
                    v1 = fmaxf((v1 - mn) * sc + bt, 0.0f);
                }
                *(float2*)(Y + rowb + n) = make_float2(v0, v1);
            }
        }
    }
}

// ---------------- small projection: O=16, I=128 (pq / pk) ----------------
__global__ __launch_bounds__(256) void proj16_kernel(
    const float* __restrict__ Wm, const float* __restrict__ bias,
    const float* __restrict__ X, float* __restrict__ Y)
{
    __shared__ float Ws[16 * 128];
    const int b = blockIdx.y;
    const int p = blockIdx.x * 256 + threadIdx.x;
    for (int i = threadIdx.x; i < 2048; i += 256) Ws[i] = Wm[i];
    __syncthreads();
    float acc[16];
#pragma unroll
    for (int o = 0; o < 16; o++) acc[o] = bias[o];
    const float* Xp = X + (size_t)b * 128 * HWSZ + p;
#pragma unroll 4
    for (int i = 0; i < 128; i++) {
        float xv = Xp[(size_t)i * HWSZ];
#pragma unroll
        for (int o = 0; o < 16; o++) acc[o] += Ws[o * 128 + i] * xv;
    }
    float* Yp = Y + (size_t)b * 16 * HWSZ + p;
#pragma unroll
    for (int o = 0; o < 16; o++) Yp[(size_t)o * HWSZ] = acc[o];
}

// ---------------- criss-cross logits (fp32 SIMT, K=16 only) ----------------
__global__ __launch_bounds__(256) void eH_kernel(const float* __restrict__ pq,
                                                 const float* __restrict__ pk,
                                                 float* __restrict__ att)
{
    __shared__ float PQ[16][128];
    __shared__ float PK[16][128];
    const int w = blockIdx.x, b = blockIdx.y;
    for (int i = threadIdx.x; i < 2048; i += 256) {
        int c = i >> 7, h = i & 127;
        size_t idx = (((size_t)b * 16 + c) * 128 + h) * 128 + w;
        PQ[c][h] = pq[idx];
        PK[c][h] = pk[idx];
    }
    __syncthreads();
    const int x  = threadIdx.x & 127;
    const int h0 = threadIdx.x >> 7;
    for (int h = h0; h < 128; h += 2) {
        float s = 0.0f;
#pragma unroll
        for (int c = 0; c < 16; c++) s += PQ[c][h] * PK[c][x];
        if (h == x) s += NEGINF;
        att[(((size_t)b * 128 + h) * 128 + w) * 256 + x] = s;
    }
}

__global__ __launch_bounds__(256) void eW_kernel(const float* __restrict__ pq,
                                                 const float* __restrict__ pk,
                                                 float* __restrict__ att)
{
    __shared__ float PQ[16][128];
    __shared__ float PK[16][128];
    const int h = blockIdx.x, b = blockIdx.y;
    for (int i = threadIdx.x; i < 2048; i += 256) {
        int c = i >> 7, w = i & 127;
        size_t idx = (((size_t)b * 16 + c) * 128 + h) * 128 + w;
        PQ[c][w] = pq[idx];
        PK[c][w] = pk[idx];
    }
    __syncthreads();
    const int x  = threadIdx.x & 127;
    const int w0 = threadIdx.x >> 7;
    for (int w = w0; w < 128; w += 2) {
        float s = 0.0f;
#pragma unroll
        for (int c = 0; c < 16; c++) s += PQ[c][w] * PK[c][x];
        att[(((size_t)b * 128 + h) * 128 + w) * 256 + 128 + x] = s;
    }
}

// ---------------- softmax over last dim (256), one warp per row ----------------
__global__ __launch_bounds__(256) void softmax_kernel(float* __restrict__ att)
{
    const int warp = threadIdx.x >> 5;
    const int lane = threadIdx.x & 31;
    const size_t row = (size_t)blockIdx.x * 8 + warp;
    float* r = att + row * 256;
    float v[8];
    float mx = -INFINITY;
#pragma unroll
    for (int j = 0; j < 8; j++) { v[j] = r[lane + 32 * j]; mx = fmaxf(mx, v[j]); }
#pragma unroll
    for (int o = 16; o; o >>= 1) mx = fmaxf(mx, __shfl_xor_sync(0xffffffffu, mx, o));
    float s = 0.0f;
#pragma unroll
    for (int j = 0; j < 8; j++) { v[j] = __expf(v[j] - mx); s += v[j]; }
#pragma unroll
    for (int o = 16; o; o >>= 1) s += __shfl_xor_sync(0xffffffffu, s, o);
    float inv = 1.0f / s;
#pragma unroll
    for (int j = 0; j < 8; j++) r[lane + 32 * j] = v[j] * inv;
}

// ---------------- aggH: tmp[b,c,h,w] = sum_x pv[b,c,x,w]*attH[b,h,w,x] (tf32 mma) ----------------
__global__ __launch_bounds__(256) void aggH_mma(const float* __restrict__ pv,
                                                const float* __restrict__ att,
                                                float* __restrict__ tmp)
{
    __shared__ unsigned As[16][136];
    __shared__ unsigned Bs[16][136];
    const int w = blockIdx.x, b = blockIdx.y;
    const int tid  = threadIdx.x;
    const int warp = tid >> 5;
    const int lane = tid & 31;
    const int mbase = (warp >> 2) * 64;
    const int nbase = (warp & 3) * 32;

    const int cm = tid >> 1;          // staging row (c for A, h for B)
    const int xq = (tid & 1) * 8;

    float acc[4][4][4] = {};

    const float* pvp = pv + (((size_t)b * 128 + cm) * 128) * 128 + w;             // + x*128
    const float* atp = att + (((size_t)b * 128 + cm) * 128 + w) * 256;            // + x

    for (int k0 = 0; k0 < 128; k0 += 16) {
        // A: pv[b, c=cm, x=k0+xq+j, w] (strided, L2-resident)
        float av[8];
#pragma unroll
        for (int j = 0; j < 8; j++) av[j] = pvp[(size_t)(k0 + xq + j) * 128];
        // B: att[b, h=cm, w, x] contiguous
        float4 b0 = *(const float4*)(atp + k0 + xq);
        float4 b1 = *(const float4*)(atp + k0 + xq + 4);

        __syncthreads();
#pragma unroll
        for (int j = 0; j < 8; j++) As[xq + j][cm] = f2tf(av[j]);
        Bs[xq + 0][cm] = f2tf(b0.x);
        Bs[xq + 1][cm] = f2tf(b0.y);
        Bs[xq + 2][cm] = f2tf(b0.z);
        Bs[xq + 3][cm] = f2tf(b0.w);
        Bs[xq + 4][cm] = f2tf(b1.x);
        Bs[xq + 5][cm] = f2tf(b1.y);
        Bs[xq + 6][cm] = f2tf(b1.z);
        Bs[xq + 7][cm] = f2tf(b1.w);
        __syncthreads();

        tile_mma(As, Bs, acc, lane, mbase, nbase);
    }

#pragma unroll
    for (int mt = 0; mt < 4; mt++)
#pragma unroll
        for (int half = 0; half < 2; half++) {
            int c = mbase + mt * 16 + (lane >> 2) + half * 8;
            size_t cb = (((size_t)b * 128 + c) * 128) * 128 + w;
#pragma unroll
            for (int nt = 0; nt < 4; nt++) {
                int h = nbase + nt * 8 + 2 * (lane & 3);
                tmp[cb + (size_t)h * 128]       = acc[mt][nt][half * 2 + 0];
                tmp[cb + (size_t)(h + 1) * 128] = acc[mt][nt][half * 2 + 1];
            }
        }
}

// ---------------- aggW + update: value += gamma*(tmp + sum_x pv[b,c,h,x]*attW[b,h,w,x]) ----------------
__global__ __launch_bounds__(256) void aggW_mma(const float* __restrict__ pv,
                                                const float* __restrict__ att,
                                                const float* __restrict__ tmp,
                                                float* __restrict__ value,
                                                const float* __restrict__ gamma_p)
{
    __shared__ unsigned As[16][136];
    __shared__ unsigned Bs[16][136];
    const int h = blockIdx.x, b = blockIdx.y;
    const int tid  = threadIdx.x;
    const int warp = tid >> 5;
    const int lane = tid & 31;
    const int mbase = (warp >> 2) * 64;
    const int nbase = (warp & 3) * 32;

    const int cm = tid >> 1;          // c for A, w for B
    const int xq = (tid & 1) * 8;

    float acc[4][4][4] = {};

    const float* pvp = pv + (((size_t)b * 128 + cm) * 128 + h) * 128;             // + x
    const float* atp = att + (((size_t)b * 128 + h) * 128 + cm) * 256 + 128;      // + x

    for (int k0 = 0; k0 < 128; k0 += 16) {
        float4 a0 = *(const float4*)(pvp + k0 + xq);
        float4 a1 = *(const float4*)(pvp + k0 + xq + 4);
        float4 b0 = *(const float4*)(atp + k0 + xq);
        float4 b1 = *(const float4*)(atp + k0 + xq + 4);

        __syncthreads();
        As[xq + 0][cm] = f2tf(a0.x);
        As[xq + 1][cm] = f2tf(a0.y);
        As[xq + 2][cm] = f2tf(a0.z);
        As[xq + 3][cm] = f2tf(a0.w);
        As[xq + 4][cm] = f2tf(a1.x);
        As[xq + 5][cm] = f2tf(a1.y);
        As[xq + 6][cm] = f2tf(a1.z);
        As[xq + 7][cm] = f2tf(a1.w);
        Bs[xq + 0][cm] = f2tf(b0.x);
        Bs[xq + 1][cm] = f2tf(b0.y);
        Bs[xq + 2][cm] = f2tf(b0.z);
        Bs[xq + 3][cm] = f2tf(b0.w);
        Bs[xq + 4][cm] = f2tf(b1.x);
        Bs[xq + 5][cm] = f2tf(b1.y);
        Bs[xq + 6][cm] = f2tf(b1.z);
        Bs[xq + 7][cm] = f2tf(b1.w);
        __syncthreads();

        tile_mma(As, Bs, acc, lane, mbase, nbase);
    }

    const float g = *gamma_p;
#pragma unroll
    for (int mt = 0; mt < 4; mt++)
#pragma unroll
        for (int half = 0; half < 2; half++) {
            int c = mbase + mt * 16 + (lane >> 2) + half * 8;
            size_t rowb = (((size_t)b * 128 + c) * 128 + h) * 128;
#pragma unroll
            for (int nt = 0; nt < 4; nt++) {
                int n = nbase + nt * 8 + 2 * (lane & 3);
                float2 t = *(const float2*)(tmp + rowb + n);
                float2 v = *(const float2*)(value + rowb + n);
                v.x += g * (t.x + acc[mt][nt][half * 2 + 0]);
                v.y += g * (t.y + acc[mt][nt][half * 2 + 1]);
                *(float2*)(value + rowb + n) = v;
            }
        }
}

// ---------------- launch ----------------
extern "C" void kernel_launch(void* const* d_in, const int* in_sizes, int n_in,
                              void* d_out, int out_size)
{
    const float* low   = (const float*)d_in[0];
    const float* high  = (const float*)d_in[1];
    const float* Wc1   = (const float*)d_in[2];
    const float* bc1   = (const float*)d_in[3];
    const float* Wc2   = (const float*)d_in[4];
    const float* bc2   = (const float*)d_in[5];
    const float* Wq    = (const float*)d_in[6];
    const float* bq    = (const float*)d_in[7];
    const float* Wk    = (const float*)d_in[8];
    const float* bk    = (const float*)d_in[9];
    const float* Wv    = (const float*)d_in[10];
    const float* bv    = (const float*)d_in[11];
    const float* gamma = (const float*)d_in[12];
    const float* Wb    = (const float*)d_in[13];
    const float* bng   = (const float*)d_in[14];
    const float* bnb   = (const float*)d_in[15];
    const float* bnm   = (const float*)d_in[16];
    const float* bnv   = (const float*)d_in[17];
    float* out = (float*)d_out;

    float *highup, *query, *value, *pv, *tmp, *pq, *pk, *att;
    cudaGetSymbolAddress((void**)&highup, g_highup);
    cudaGetSymbolAddress((void**)&query,  g_query);
    cudaGetSymbolAddress((void**)&value,  g_value);
    cudaGetSymbolAddress((void**)&pv,     g_pv);
    cudaGetSymbolAddress((void**)&tmp,    g_tmp);
    cudaGetSymbolAddress((void**)&pq,     g_pq);
    cudaGetSymbolAddress((void**)&pk,     g_pk);
    cudaGetSymbolAddress((void**)&att,    g_att);

    // 1. bilinear 2x upsample
    upsample_kernel<<<65536, 256>>>(high, highup);

    // 2. query = Wc1 @ concat(highup, low) + bc1  (single fused dual-input GEMM)
    gemm_dual<<<dim3(128, 1, BB), 256>>>(Wc1, 512, bc1, highup, 256, low, 256,
                                         query, 128, nullptr, nullptr, nullptr, nullptr);
    // 3. value = Wc2 @ highup + bc2
    gemm_dual<<<dim3(128, 1, BB), 256>>>(Wc2, 256, bc2, highup, 256, nullptr, 0,
                                         value, 128, nullptr, nullptr, nullptr, nullptr);

    // 4. pq (query fixed across iterations)
    proj16_kernel<<<dim3(64, BB), 256>>>(Wq, bq, query, pq);

    // 5. two criss-cross attention iterations
    for (int it = 0; it < 2; it++) {
        proj16_kernel<<<dim3(64, BB), 256>>>(Wk, bk, value, pk);
        gemm_dual<<<dim3(128, 1, BB), 256>>>(Wv, 128, bv, value, 128, nullptr, 0,
                                             pv, 128, nullptr, nullptr, nullptr, nullptr);
        eH_kernel<<<dim3(128, BB), 256>>>(pq, pk, att);
        eW_kernel<<<dim3(128, BB), 256>>>(pq, pk, att);
        softmax_kernel<<<8192, 256>>>(att);
        aggH_mma<<<dim3(128, BB), 256>>>(pv, att, tmp);
        aggW_mma<<<dim3(128, BB), 256>>>(pv, att, tmp, value, gamma);
    }

    // 6. out = BN(ReLU(Wb @ concat(value, highup)))  (single fused dual-input GEMM)
    gemm_dual<<<dim3(128, 2, BB), 256>>>(Wb, 384, nullptr, value, 128, highup, 256,
                                         out, 256, bng, bnb, bnm, bnv);
}